// round 3
// baseline (speedup 1.0000x reference)
#include <cuda_runtime.h>
#include <math.h>
#include <limits.h>

// Problem constants (per reference): B=4096, DIM=512, C=128, TEMP=0.05
#define MAXB 8192
#define MAXC 256
#define DIM  512
#define NREG (DIM / 32)   // 16 floats per lane

__device__ int   g_lab[MAXB];        // labels as int32
__device__ int   g_bstart[MAXC + 1]; // CSR bucket starts
__device__ int   g_bidx[MAXB];       // indices grouped by label
__device__ float g_sum;
__device__ float g_cnt;

// ---------------------------------------------------------------------------
// Kernel 1: build label buckets (CSR) + zero accumulators. Single block.
// ---------------------------------------------------------------------------
__global__ void build_kernel(const int* __restrict__ labels, int n, int C)
{
    __shared__ int s_cnt[MAXC];
    __shared__ int s_off[MAXC];
    int tid = threadIdx.x;

    for (int c = tid; c < MAXC; c += blockDim.x) s_cnt[c] = 0;
    if (tid == 0) { g_sum = 0.0f; g_cnt = 0.0f; }
    __syncthreads();

    for (int i = tid; i < n; i += blockDim.x) {
        int l = labels[i];
        if (l < 0) l = 0;
        if (l >= C) l = C - 1;     // defensive clamp
        g_lab[i] = l;
        atomicAdd(&s_cnt[l], 1);
    }
    __syncthreads();

    if (tid == 0) {
        int acc = 0;
        for (int c = 0; c < C; c++) {
            s_off[c]    = acc;
            g_bstart[c] = acc;
            acc += s_cnt[c];
        }
        g_bstart[C] = acc;
    }
    __syncthreads();

    for (int i = tid; i < n; i += blockDim.x) {
        int l = g_lab[i];
        int p = atomicAdd(&s_off[l], 1);
        g_bidx[p] = i;
    }
}

// ---------------------------------------------------------------------------
// Kernel 2: one warp per triplet, triplets visited in bucket order.
// ---------------------------------------------------------------------------
__device__ __forceinline__ float warp_sum(float v)
{
    #pragma unroll
    for (int o = 16; o > 0; o >>= 1)
        v += __shfl_xor_sync(0xFFFFFFFFu, v, o);
    return v;
}

__global__ void __launch_bounds__(256)
triplet_kernel(const float* __restrict__ batch,
               const int* __restrict__ anchors,
               const int* __restrict__ negatives,
               int n)
{
    int gw   = (blockIdx.x * blockDim.x + threadIdx.x) >> 5;
    int lane = threadIdx.x & 31;
    if (gw >= n) return;

    int t   = g_bidx[gw];          // triplet/row index (bucket order for locality)
    int lab = g_lab[t];
    int s   = g_bstart[lab];
    int e   = g_bstart[lab + 1];
    int cnt = e - s;               // bucket size; positives for row t = cnt-1

    // row t in registers
    float xi[NREG];
    const float* rt = batch + (size_t)t * DIM;
    #pragma unroll
    for (int k = 0; k < NREG; k++) xi[k] = rt[lane + 32 * k];

    // hardest (closest) positive: min direct squared distance, first-index ties
    float best  = INFINITY;
    int   bestj = INT_MAX;
    for (int p = s; p < e; p++) {
        int j = g_bidx[p];
        if (j == t) continue;
        const float* rj = batch + (size_t)j * DIM;
        float acc = 0.0f;
        #pragma unroll
        for (int k = 0; k < NREG; k++) {
            float d = xi[k] - rj[lane + 32 * k];
            acc = fmaf(d, d, acc);
        }
        acc = warp_sum(acc);       // all lanes hold the same value
        if (acc < best || (acc == best && j < bestj)) { best = acc; bestj = j; }
    }

    bool valid = (cnt > 2);        // sum(posmask) > 1
    if (!valid) return;

    int a  = anchors[t];
    int ng = negatives[t];

    // d_ap = ||batch[a] - batch[bestj]||  (a == t in this dataset, reuse best)
    float dap2;
    if (a == t) {
        dap2 = best;
    } else {
        const float* ra = batch + (size_t)a * DIM;
        const float* rp = batch + (size_t)bestj * DIM;
        float acc = 0.0f;
        #pragma unroll
        for (int k = 0; k < NREG; k++) {
            float d = ra[lane + 32 * k] - rp[lane + 32 * k];
            acc = fmaf(d, d, acc);
        }
        dap2 = warp_sum(acc);
    }

    // d_an = ||batch[a] - batch[ng]||
    float dan2;
    {
        const float* rn = batch + (size_t)ng * DIM;
        float acc = 0.0f;
        if (a == t) {
            #pragma unroll
            for (int k = 0; k < NREG; k++) {
                float d = xi[k] - rn[lane + 32 * k];
                acc = fmaf(d, d, acc);
            }
        } else {
            const float* ra = batch + (size_t)a * DIM;
            #pragma unroll
            for (int k = 0; k < NREG; k++) {
                float d = ra[lane + 32 * k] - rn[lane + 32 * k];
                acc = fmaf(d, d, acc);
            }
        }
        dan2 = warp_sum(acc);
    }

    if (lane == 0) {
        float d_ap = sqrtf(fmaxf(dap2, 1e-12f));
        float d_an = sqrtf(fmaxf(dan2, 1e-12f));
        float s_ap = 1.0f - 0.5f * d_ap;
        float s_an = 1.0f - 0.5f * d_an;
        float z    = (s_an - s_ap) / 0.05f;
        // numerically stable softplus
        float per  = fmaxf(z, 0.0f) + log1pf(expf(-fabsf(z)));
        atomicAdd(&g_sum, per);
        atomicAdd(&g_cnt, 1.0f);
    }
}

// ---------------------------------------------------------------------------
// Kernel 3: finalize
// ---------------------------------------------------------------------------
__global__ void finalize_kernel(float* __restrict__ out)
{
    out[0] = g_sum / g_cnt;
}

// ---------------------------------------------------------------------------
extern "C" void kernel_launch(void* const* d_in, const int* in_sizes, int n_in,
                              void* d_out, int out_size)
{
    const float* batch     = (const float*)d_in[0];
    const int*   labels    = (const int*)d_in[1];
    const int*   anchors   = (const int*)d_in[2];
    const int*   negatives = (const int*)d_in[3];
    float*       out       = (float*)d_out;

    int n = in_sizes[1];   // number of rows / triplets
    int C = 128;

    build_kernel<<<1, 1024>>>(labels, n, C);

    int warps_per_block = 256 / 32;
    int grid = (n + warps_per_block - 1) / warps_per_block;
    triplet_kernel<<<grid, 256>>>(batch, anchors, negatives, n);

    finalize_kernel<<<1, 1>>>(out);
}

// round 4
// speedup vs baseline: 1.4158x; 1.4158x over previous
#include <cuda_runtime.h>
#include <math.h>
#include <limits.h>

// Problem constants (per reference): B=4096, DIM=512, C=128, TEMP=0.05
#define MAXB 8192
#define MAXC 128
#define DIM  512
#define NV4  (DIM / 4)    // 128 float4 per row

__device__ int   g_lab[MAXB];        // labels as int32
__device__ int   g_bstart[MAXC + 1]; // CSR bucket starts
__device__ int   g_bidx[MAXB];       // row indices grouped by label
__device__ float g_sum;
__device__ float g_cnt;
__device__ int   g_done;

// ---------------------------------------------------------------------------
// Kernel 1: build label buckets (CSR) + zero accumulators. Single block.
// ---------------------------------------------------------------------------
__global__ void __launch_bounds__(1024)
build_kernel(const int* __restrict__ labels, int n, int C)
{
    __shared__ int s_cnt[MAXC];
    __shared__ int s_scat[MAXC];
    __shared__ int s_wsum[4];
    __shared__ int s_lab[MAXB];
    int tid = threadIdx.x;

    for (int c = tid; c < MAXC; c += blockDim.x) s_cnt[c] = 0;
    if (tid == 0) { g_sum = 0.0f; g_cnt = 0.0f; g_done = 0; }
    __syncthreads();

    for (int i = tid; i < n; i += blockDim.x) {
        int l = labels[i];
        l = (l < 0) ? 0 : (l >= C ? C - 1 : l);
        s_lab[i] = l;
        g_lab[i] = l;
        atomicAdd(&s_cnt[l], 1);
    }
    __syncthreads();

    // parallel prefix over 128 bins: 4-warp shfl scan + cross-warp fixup
    int incl_local = 0;
    if (tid < MAXC) {
        int lane = tid & 31, w = tid >> 5;
        int x = s_cnt[tid];
        #pragma unroll
        for (int o = 1; o < 32; o <<= 1) {
            int y = __shfl_up_sync(0xFFFFFFFFu, x, o);
            if (lane >= o) x += y;
        }
        if (lane == 31) s_wsum[w] = x;
        incl_local = x;
    }
    __syncthreads();
    if (tid < MAXC) {
        int w = tid >> 5;
        int add = 0;
        #pragma unroll
        for (int k = 0; k < 4; k++) add += (k < w) ? s_wsum[k] : 0;
        int incl = incl_local + add;
        int excl = incl - s_cnt[tid];
        g_bstart[tid] = excl;
        s_scat[tid]   = excl;
        if (tid == MAXC - 1) g_bstart[MAXC] = incl;
    }
    __syncthreads();

    for (int i = tid; i < n; i += blockDim.x) {
        int l = s_lab[i];
        int p = atomicAdd(&s_scat[l], 1);
        g_bidx[p] = i;
    }
}

// ---------------------------------------------------------------------------
// Kernel 2: one warp per triplet (bucket order); last block finalizes.
// ---------------------------------------------------------------------------
__device__ __forceinline__ float warp_sum(float v)
{
    #pragma unroll
    for (int o = 16; o > 0; o >>= 1)
        v += __shfl_xor_sync(0xFFFFFFFFu, v, o);
    return v;
}

__device__ __forceinline__ float lane_d2(const float4 xi[4],
                                         const float4* __restrict__ rj, int lane)
{
    float4 a0 = rj[lane];
    float4 a1 = rj[lane + 32];
    float4 a2 = rj[lane + 64];
    float4 a3 = rj[lane + 96];
    float c0, c1, c2, c3, d;
    d = xi[0].x - a0.x; c0 = d * d;
    d = xi[1].x - a1.x; c1 = d * d;
    d = xi[2].x - a2.x; c2 = d * d;
    d = xi[3].x - a3.x; c3 = d * d;
    d = xi[0].y - a0.y; c0 = fmaf(d, d, c0);
    d = xi[1].y - a1.y; c1 = fmaf(d, d, c1);
    d = xi[2].y - a2.y; c2 = fmaf(d, d, c2);
    d = xi[3].y - a3.y; c3 = fmaf(d, d, c3);
    d = xi[0].z - a0.z; c0 = fmaf(d, d, c0);
    d = xi[1].z - a1.z; c1 = fmaf(d, d, c1);
    d = xi[2].z - a2.z; c2 = fmaf(d, d, c2);
    d = xi[3].z - a3.z; c3 = fmaf(d, d, c3);
    d = xi[0].w - a0.w; c0 = fmaf(d, d, c0);
    d = xi[1].w - a1.w; c1 = fmaf(d, d, c1);
    d = xi[2].w - a2.w; c2 = fmaf(d, d, c2);
    d = xi[3].w - a3.w; c3 = fmaf(d, d, c3);
    return (c0 + c1) + (c2 + c3);
}

__global__ void __launch_bounds__(256)
triplet_kernel(const float* __restrict__ batch,
               const int* __restrict__ anchors,
               const int* __restrict__ negatives,
               int n, float* __restrict__ out)
{
    int gw   = (blockIdx.x * blockDim.x + threadIdx.x) >> 5;
    int lane = threadIdx.x & 31;

    if (gw < n) {
        int t   = g_bidx[gw];          // triplet/row index (bucket order)
        int lab = g_lab[t];
        int s   = g_bstart[lab];
        int e   = g_bstart[lab + 1];
        int cnt = e - s;

        // row t in registers (as 4 float4 per lane)
        const float4* rt = (const float4*)(batch + (size_t)t * DIM);
        float4 xi[4];
        xi[0] = rt[lane];
        xi[1] = rt[lane + 32];
        xi[2] = rt[lane + 64];
        xi[3] = rt[lane + 96];

        // hardest (closest) positive: min d^2, first-index ties
        float best  = INFINITY;
        int   bestj = INT_MAX;
        #pragma unroll 2
        for (int p = s; p < e; p++) {
            int j = g_bidx[p];
            const float4* rj = (const float4*)(batch + (size_t)j * DIM);
            float acc = lane_d2(xi, rj, lane);
            acc = warp_sum(acc);
            if (j != t && (acc < best || (acc == best && j < bestj))) {
                best = acc; bestj = j;
            }
        }

        bool valid = (cnt > 2);        // sum(posmask) > 1
        if (valid) {
            int a  = anchors[t];
            int ng = negatives[t];

            float dap2;
            if (a == t) {
                dap2 = best;
            } else {
                const float4* ra = (const float4*)(batch + (size_t)a * DIM);
                float4 xa[4];
                xa[0] = ra[lane]; xa[1] = ra[lane + 32];
                xa[2] = ra[lane + 64]; xa[3] = ra[lane + 96];
                const float4* rp = (const float4*)(batch + (size_t)bestj * DIM);
                dap2 = warp_sum(lane_d2(xa, rp, lane));
            }

            float dan2;
            {
                const float4* rn = (const float4*)(batch + (size_t)ng * DIM);
                if (a == t) {
                    dan2 = warp_sum(lane_d2(xi, rn, lane));
                } else {
                    const float4* ra = (const float4*)(batch + (size_t)a * DIM);
                    float4 xa[4];
                    xa[0] = ra[lane]; xa[1] = ra[lane + 32];
                    xa[2] = ra[lane + 64]; xa[3] = ra[lane + 96];
                    dan2 = warp_sum(lane_d2(xa, rn, lane));
                }
            }

            if (lane == 0) {
                float d_ap = sqrtf(fmaxf(dap2, 1e-12f));
                float d_an = sqrtf(fmaxf(dan2, 1e-12f));
                float s_ap = 1.0f - 0.5f * d_ap;
                float s_an = 1.0f - 0.5f * d_an;
                float z    = (s_an - s_ap) * 20.0f;   // / 0.05
                float per  = fmaxf(z, 0.0f) + log1pf(expf(-fabsf(z)));
                atomicAdd(&g_sum, per);
                atomicAdd(&g_cnt, 1.0f);
            }
        }
    }

    // fused finalize: last block to arrive writes the output
    __syncthreads();
    if (threadIdx.x == 0) {
        __threadfence();
        int done = atomicAdd(&g_done, 1);
        if (done == (int)gridDim.x - 1) {
            float sum = atomicAdd(&g_sum, 0.0f);
            float cnt = atomicAdd(&g_cnt, 0.0f);
            out[0] = sum / cnt;
        }
    }
}

// ---------------------------------------------------------------------------
extern "C" void kernel_launch(void* const* d_in, const int* in_sizes, int n_in,
                              void* d_out, int out_size)
{
    const float* batch     = (const float*)d_in[0];
    const int*   labels    = (const int*)d_in[1];
    const int*   anchors   = (const int*)d_in[2];
    const int*   negatives = (const int*)d_in[3];
    float*       out       = (float*)d_out;

    int n = in_sizes[1];   // number of rows / triplets
    int C = 128;

    build_kernel<<<1, 1024>>>(labels, n, C);

    int warps_per_block = 256 / 32;
    int grid = (n + warps_per_block - 1) / warps_per_block;
    triplet_kernel<<<grid, 256>>>(batch, anchors, negatives, n, out);
}